// round 2
// baseline (speedup 1.0000x reference)
#include <cuda_runtime.h>
#include <math.h>
#include <stdint.h>

#define D_MODEL 1024
#define NSTATE  16
#define BATCH   8
#define SEQ     4096
#define ROWS    (BATCH * SEQ)      // 32768
#define LN_EPS  1e-5f

// ---------------- scratch (device globals: allocation-free rule) ----------------
__device__ float g_xn[(size_t)ROWS * D_MODEL];   // layernormed x  (134 MB)
__device__ float g_out[(size_t)ROWS * D_MODEL];  // H @ Wo^T + bo  (134 MB)
__device__ float g_u[(size_t)ROWS * NSTATE];     // drive           (2 MB)
__device__ float g_H[(size_t)ROWS * NSTATE];     // scan states     (2 MB)
__device__ float g_Wsum[NSTATE * D_MODEL];
__device__ float g_bsum[NSTATE];

// ---------------- K0: Wsum = Ws + Wi, bsum = bs + bi ----------------
__global__ void k0_prep(const float* __restrict__ Ws, const float* __restrict__ Wi,
                        const float* __restrict__ bs, const float* __restrict__ bi) {
    int i = blockIdx.x * blockDim.x + threadIdx.x;
    if (i < NSTATE * D_MODEL) g_Wsum[i] = Ws[i] + Wi[i];
    if (i < NSTATE)           g_bsum[i] = bs[i] + bi[i];
}

// ---------------- K1: LayerNorm + u = xn @ Wsum^T + bsum ----------------
// one block (256 threads) per row; each thread owns 4 contiguous elements
__global__ __launch_bounds__(256) void k1_ln_u(const float* __restrict__ x,
                                               const float* __restrict__ ln_w,
                                               const float* __restrict__ ln_b) {
    const int row = blockIdx.x;
    const int t   = threadIdx.x;
    const int lid = t & 31, wid = t >> 5;

    const float4 v = ((const float4*)(x + (size_t)row * D_MODEL))[t];
    float s  = (v.x + v.y) + (v.z + v.w);
    float sq = v.x * v.x + v.y * v.y + v.z * v.z + v.w * v.w;

    #pragma unroll
    for (int o = 16; o > 0; o >>= 1) {
        s  += __shfl_xor_sync(0xffffffffu, s,  o);
        sq += __shfl_xor_sync(0xffffffffu, sq, o);
    }
    __shared__ float redS[8], redQ[8];
    if (lid == 0) { redS[wid] = s; redQ[wid] = sq; }
    __syncthreads();
    s = 0.f; sq = 0.f;
    #pragma unroll
    for (int w = 0; w < 8; w++) { s += redS[w]; sq += redQ[w]; }

    const float mu   = s * (1.f / D_MODEL);
    const float var  = fmaxf(sq * (1.f / D_MODEL) - mu * mu, 0.f);
    const float rstd = rsqrtf(var + LN_EPS);

    const float4 w4 = ((const float4*)ln_w)[t];
    const float4 b4 = ((const float4*)ln_b)[t];
    float4 xn;
    xn.x = (v.x - mu) * rstd * w4.x + b4.x;
    xn.y = (v.y - mu) * rstd * w4.y + b4.y;
    xn.z = (v.z - mu) * rstd * w4.z + b4.z;
    xn.w = (v.w - mu) * rstd * w4.w + b4.w;
    ((float4*)(g_xn + (size_t)row * D_MODEL))[t] = xn;

    // u partials: 16 state projections
    float acc[NSTATE];
    #pragma unroll
    for (int nn = 0; nn < NSTATE; nn++) {
        const float4 wv = ((const float4*)(g_Wsum + nn * D_MODEL))[t];
        float a = xn.x * wv.x;
        a = fmaf(xn.y, wv.y, a);
        a = fmaf(xn.z, wv.z, a);
        a = fmaf(xn.w, wv.w, a);
        #pragma unroll
        for (int o = 16; o > 0; o >>= 1) a += __shfl_xor_sync(0xffffffffu, a, o);
        acc[nn] = a;
    }
    __shared__ float us[8][NSTATE];
    if (lid == 0) {
        #pragma unroll
        for (int nn = 0; nn < NSTATE; nn++) us[wid][nn] = acc[nn];
    }
    __syncthreads();
    if (t < NSTATE) {
        float ua = g_bsum[t];
        #pragma unroll
        for (int w = 0; w < 8; w++) ua += us[w][t];
        g_u[(size_t)row * NSTATE + t] = ua;
    }
}

// ---------------- K2: sequential scan h_t = tanh(A h_{t-1} + u_t) ----------------
// 4 blocks x 32 threads; each warp = 2 batches x 16 state-lanes (shfl width 16)
__global__ __launch_bounds__(32) void k2_scan(const float* __restrict__ A) {
    const int lane = threadIdx.x;
    const int n = lane & 15;
    const int b = blockIdx.x * 2 + (lane >> 4);

    float Ar[16];
    #pragma unroll
    for (int j = 0; j < 16; j++) Ar[j] = A[n * 16 + j];

    const float* __restrict__ ub = g_u + (size_t)b * SEQ * NSTATE + n;
    float* __restrict__       Hb = g_H + (size_t)b * SEQ * NSTATE + n;

    float h = 0.f;
    float ur[8];
    #pragma unroll
    for (int k = 0; k < 8; k++) ur[k] = ub[k * NSTATE];

    #pragma unroll 1
    for (int t0 = 0; t0 < SEQ; t0 += 8) {
        #pragma unroll
        for (int k = 0; k < 8; k++) {
            float pre = ur[k];
            const int tn = t0 + 8 + k;
            if (tn < SEQ) ur[k] = ub[(size_t)tn * NSTATE];  // prefetch 8 steps ahead

            float a0 = 0.f, a1 = 0.f, a2 = 0.f, a3 = 0.f;
            #pragma unroll
            for (int j = 0; j < 4; j++) {
                a0 = fmaf(Ar[j +  0], __shfl_sync(0xffffffffu, h, j +  0, 16), a0);
                a1 = fmaf(Ar[j +  4], __shfl_sync(0xffffffffu, h, j +  4, 16), a1);
                a2 = fmaf(Ar[j +  8], __shfl_sync(0xffffffffu, h, j +  8, 16), a2);
                a3 = fmaf(Ar[j + 12], __shfl_sync(0xffffffffu, h, j + 12, 16), a3);
            }
            pre += (a0 + a1) + (a2 + a3);
            pre = fminf(pre, 30.f);                 // avoid exp overflow -> NaN
            const float e = __expf(pre + pre);      // e^(2x)
            h = __fdividef(e - 1.f, e + 1.f);       // tanh, ~1e-7 abs err
            Hb[(size_t)(t0 + k) * NSTATE] = h;
        }
    }
}

// ---------------- K2b: g_out = H @ Wo^T + bo ----------------
// one block per 16 rows; thread t owns output cols [4t, 4t+4)
__global__ __launch_bounds__(256) void k2b_out(const float* __restrict__ Wo,
                                               const float* __restrict__ bo) {
    const int t  = threadIdx.x;
    const int r0 = blockIdx.x * 16;

    __shared__ float hs[16][NSTATE];
    if (t < 64)
        ((float4*)&hs[0][0])[t] = ((const float4*)(g_H + (size_t)r0 * NSTATE))[t];

    const int d0 = t * 4;
    float wo[4][NSTATE];
    #pragma unroll
    for (int dd = 0; dd < 4; dd++) {
        #pragma unroll
        for (int c4 = 0; c4 < 4; c4++) {
            float4 wv = ((const float4*)(Wo + (size_t)(d0 + dd) * NSTATE))[c4];
            wo[dd][c4 * 4 + 0] = wv.x; wo[dd][c4 * 4 + 1] = wv.y;
            wo[dd][c4 * 4 + 2] = wv.z; wo[dd][c4 * 4 + 3] = wv.w;
        }
    }
    const float4 bov = ((const float4*)bo)[t];
    __syncthreads();

    #pragma unroll 1
    for (int r = 0; r < 16; r++) {
        float o0 = bov.x, o1 = bov.y, o2 = bov.z, o3 = bov.w;
        #pragma unroll
        for (int nn = 0; nn < NSTATE; nn++) {
            const float hv = hs[r][nn];
            o0 = fmaf(hv, wo[0][nn], o0);
            o1 = fmaf(hv, wo[1][nn], o1);
            o2 = fmaf(hv, wo[2][nn], o2);
            o3 = fmaf(hv, wo[3][nn], o3);
        }
        ((float4*)(g_out + (size_t)(r0 + r) * D_MODEL))[t] = make_float4(o0, o1, o2, o3);
    }
}

// ---------------- K3: y = sigmoid(xn @ Wg^T + bg) * g_out + x ----------------
// 128x128x16 SGEMM tile, 256 threads, 8x8 micro-tile (split 4+4), double-buffered smem
__global__ __launch_bounds__(256, 2) void k3_gemm(const float* __restrict__ Wg,
                                                  const float* __restrict__ bg,
                                                  const float* __restrict__ x,
                                                  float* __restrict__ out) {
    __shared__ __align__(16) float sm[8448];   // As[2][16][132] | Bs[2][16][132]
    #define AS(b, k, m) sm[(b) * 2112 + (k) * 132 + (m)]
    #define BS(b, k, n) sm[4224 + (b) * 2112 + (k) * 132 + (n)]

    const int tid = threadIdx.x;
    const int m0 = blockIdx.y * 128;
    const int n0 = blockIdx.x * 128;

    const int aRow = tid >> 2;            // 0..63
    const int aCol = (tid & 3) << 2;      // 0,4,8,12  (k within tile)
    const int bN   = tid >> 1;            // 0..127
    const int bK   = (tid & 1) << 3;      // 0 or 8

    const float* Ap = g_xn + (size_t)(m0 + aRow) * D_MODEL + aCol;
    const float* Bp = Wg   + (size_t)(n0 + bN)   * D_MODEL + bK;

    const int txc = (tid & 15) << 2;      // col base (0..60)
    const int tyc = (tid >> 4) << 2;      // row base (0..60)

    float acc[8][8];
    #pragma unroll
    for (int i = 0; i < 8; i++)
        #pragma unroll
        for (int j = 0; j < 8; j++) acc[i][j] = 0.f;

    float4 ra0, ra1, rb0, rb1;
    // prologue: tile 0
    ra0 = *(const float4*)(Ap);
    ra1 = *(const float4*)(Ap + (size_t)64 * D_MODEL);
    rb0 = *(const float4*)(Bp);
    rb1 = *(const float4*)(Bp + 4);
    AS(0, aCol + 0, aRow) = ra0.x; AS(0, aCol + 1, aRow) = ra0.y;
    AS(0, aCol + 2, aRow) = ra0.z; AS(0, aCol + 3, aRow) = ra0.w;
    AS(0, aCol + 0, aRow + 64) = ra1.x; AS(0, aCol + 1, aRow + 64) = ra1.y;
    AS(0, aCol + 2, aRow + 64) = ra1.z; AS(0, aCol + 3, aRow + 64) = ra1.w;
    BS(0, bK + 0, bN) = rb0.x; BS(0, bK + 1, bN) = rb0.y;
    BS(0, bK + 2, bN) = rb0.z; BS(0, bK + 3, bN) = rb0.w;
    BS(0, bK + 4, bN) = rb1.x; BS(0, bK + 5, bN) = rb1.y;
    BS(0, bK + 6, bN) = rb1.z; BS(0, bK + 7, bN) = rb1.w;
    __syncthreads();

    int buf = 0;
    #pragma unroll 1
    for (int kt = 0; kt < 64; kt++) {
        if (kt < 63) {
            const float* Ak = Ap + (kt + 1) * 16;
            const float* Bk = Bp + (kt + 1) * 16;
            ra0 = *(const float4*)(Ak);
            ra1 = *(const float4*)(Ak + (size_t)64 * D_MODEL);
            rb0 = *(const float4*)(Bk);
            rb1 = *(const float4*)(Bk + 4);
        }
        #pragma unroll
        for (int k = 0; k < 16; k++) {
            const float4 A0 = *(const float4*)&AS(buf, k, tyc);
            const float4 A1 = *(const float4*)&AS(buf, k, tyc + 64);
            const float4 B0 = *(const float4*)&BS(buf, k, txc);
            const float4 B1 = *(const float4*)&BS(buf, k, txc + 64);
            const float av[8] = {A0.x, A0.y, A0.z, A0.w, A1.x, A1.y, A1.z, A1.w};
            const float bv[8] = {B0.x, B0.y, B0.z, B0.w, B1.x, B1.y, B1.z, B1.w};
            #pragma unroll
            for (int i = 0; i < 8; i++)
                #pragma unroll
                for (int j = 0; j < 8; j++)
                    acc[i][j] = fmaf(av[i], bv[j], acc[i][j]);
        }
        if (kt < 63) {
            const int nb = buf ^ 1;
            AS(nb, aCol + 0, aRow) = ra0.x; AS(nb, aCol + 1, aRow) = ra0.y;
            AS(nb, aCol + 2, aRow) = ra0.z; AS(nb, aCol + 3, aRow) = ra0.w;
            AS(nb, aCol + 0, aRow + 64) = ra1.x; AS(nb, aCol + 1, aRow + 64) = ra1.y;
            AS(nb, aCol + 2, aRow + 64) = ra1.z; AS(nb, aCol + 3, aRow + 64) = ra1.w;
            BS(nb, bK + 0, bN) = rb0.x; BS(nb, bK + 1, bN) = rb0.y;
            BS(nb, bK + 2, bN) = rb0.z; BS(nb, bK + 3, bN) = rb0.w;
            BS(nb, bK + 4, bN) = rb1.x; BS(nb, bK + 5, bN) = rb1.y;
            BS(nb, bK + 6, bN) = rb1.z; BS(nb, bK + 7, bN) = rb1.w;
        }
        __syncthreads();
        buf ^= 1;
    }

    // epilogue: gate + multiply + residual
    float bgv[8];
    #pragma unroll
    for (int j = 0; j < 8; j++) {
        const int cl = (j < 4) ? (txc + j) : (64 + txc + j - 4);
        bgv[j] = bg[n0 + cl];
    }
    #pragma unroll
    for (int i = 0; i < 8; i++) {
        const int rl = (i < 4) ? (tyc + i) : (64 + tyc + i - 4);
        const size_t base = (size_t)(m0 + rl) * D_MODEL + n0;
        const float4 o0 = *(const float4*)(g_out + base + txc);
        const float4 o1 = *(const float4*)(g_out + base + 64 + txc);
        const float4 x0 = *(const float4*)(x + base + txc);
        const float4 x1 = *(const float4*)(x + base + 64 + txc);
        const float ov[8] = {o0.x, o0.y, o0.z, o0.w, o1.x, o1.y, o1.z, o1.w};
        const float xv[8] = {x0.x, x0.y, x0.z, x0.w, x1.x, x1.y, x1.z, x1.w};
        float yv[8];
        #pragma unroll
        for (int j = 0; j < 8; j++) {
            const float g = 1.f / (1.f + __expf(-(acc[i][j] + bgv[j])));
            yv[j] = fmaf(ov[j], g, xv[j]);
        }
        *(float4*)(out + base + txc)      = make_float4(yv[0], yv[1], yv[2], yv[3]);
        *(float4*)(out + base + 64 + txc) = make_float4(yv[4], yv[5], yv[6], yv[7]);
    }
    #undef AS
    #undef BS
}

// ---------------- launch ----------------
extern "C" void kernel_launch(void* const* d_in, const int* in_sizes, int n_in,
                              void* d_out, int out_size) {
    const float* x    = (const float*)d_in[0];
    const float* Ws   = (const float*)d_in[1];
    const float* bs   = (const float*)d_in[2];
    const float* Wi   = (const float*)d_in[3];
    const float* bi   = (const float*)d_in[4];
    const float* Wo   = (const float*)d_in[5];
    const float* bo   = (const float*)d_in[6];
    const float* Wg   = (const float*)d_in[7];
    const float* bg   = (const float*)d_in[8];
    const float* ln_w = (const float*)d_in[9];
    const float* ln_b = (const float*)d_in[10];
    const float* A    = (const float*)d_in[11];
    float* out = (float*)d_out;

    k0_prep<<<64, 256>>>(Ws, Wi, bs, bi);
    k1_ln_u<<<ROWS, 256>>>(x, ln_w, ln_b);
    k2_scan<<<4, 32>>>(A);
    k2b_out<<<ROWS / 16, 256>>>(Wo, bo);
    k3_gemm<<<dim3(D_MODEL / 128, ROWS / 128), 256>>>(Wg, bg, x, out);
}

// round 4
// speedup vs baseline: 2.0494x; 2.0494x over previous
#include <cuda_runtime.h>
#include <cuda_bf16.h>
#include <math.h>
#include <stdint.h>

#define D_MODEL 1024
#define NSTATE  16
#define BATCH   8
#define SEQ     4096
#define ROWS    (BATCH * SEQ)      // 32768
#define LN_EPS  1e-5f

// ---------------- scratch (device globals: allocation-free rule) ----------------
__device__ __nv_bfloat16 g_xnb[(size_t)ROWS * D_MODEL];    // layernormed x (bf16, 67MB)
__device__ __nv_bfloat16 g_Wgb[(size_t)D_MODEL * D_MODEL]; // Wg bf16 (2MB)
__device__ float g_u[(size_t)ROWS * NSTATE];               // drive (2 MB)
__device__ float g_H[(size_t)ROWS * NSTATE];               // scan states (2 MB)
__device__ float g_Wsum[NSTATE * D_MODEL];
__device__ float g_bsum[NSTATE];

__device__ __forceinline__ uint32_t smem_u32(const void* p) {
    uint32_t a;
    asm("{ .reg .u64 t; cvta.to.shared.u64 t, %1; cvt.u32.u64 %0, t; }" : "=r"(a) : "l"(p));
    return a;
}

// ---------------- K0: Wsum = Ws + Wi, bsum = bs + bi, Wg -> bf16 ----------------
__global__ void k0_prep(const float* __restrict__ Ws, const float* __restrict__ Wi,
                        const float* __restrict__ bs, const float* __restrict__ bi,
                        const float* __restrict__ Wg) {
    int i = blockIdx.x * blockDim.x + threadIdx.x;
    if (i < D_MODEL * D_MODEL) g_Wgb[i] = __float2bfloat16_rn(Wg[i]);
    if (i < NSTATE * D_MODEL)  g_Wsum[i] = Ws[i] + Wi[i];
    if (i < NSTATE)            g_bsum[i] = bs[i] + bi[i];
}

// ---------------- K1: LayerNorm (-> bf16) + u = xn @ Wsum^T + bsum ----------------
__global__ __launch_bounds__(256) void k1_ln_u(const float* __restrict__ x,
                                               const float* __restrict__ ln_w,
                                               const float* __restrict__ ln_b) {
    const int row = blockIdx.x;
    const int t   = threadIdx.x;
    const int lid = t & 31, wid = t >> 5;

    const float4 v = ((const float4*)(x + (size_t)row * D_MODEL))[t];
    float s  = (v.x + v.y) + (v.z + v.w);
    float sq = v.x * v.x + v.y * v.y + v.z * v.z + v.w * v.w;

    #pragma unroll
    for (int o = 16; o > 0; o >>= 1) {
        s  += __shfl_xor_sync(0xffffffffu, s,  o);
        sq += __shfl_xor_sync(0xffffffffu, sq, o);
    }
    __shared__ float redS[8], redQ[8];
    if (lid == 0) { redS[wid] = s; redQ[wid] = sq; }
    __syncthreads();
    s = 0.f; sq = 0.f;
    #pragma unroll
    for (int w = 0; w < 8; w++) { s += redS[w]; sq += redQ[w]; }

    const float mu   = s * (1.f / D_MODEL);
    const float var  = fmaxf(sq * (1.f / D_MODEL) - mu * mu, 0.f);
    const float rstd = rsqrtf(var + LN_EPS);

    const float4 w4 = ((const float4*)ln_w)[t];
    const float4 b4 = ((const float4*)ln_b)[t];
    float4 xn;
    xn.x = (v.x - mu) * rstd * w4.x + b4.x;
    xn.y = (v.y - mu) * rstd * w4.y + b4.y;
    xn.z = (v.z - mu) * rstd * w4.z + b4.z;
    xn.w = (v.w - mu) * rstd * w4.w + b4.w;

    __nv_bfloat162 p0 = __floats2bfloat162_rn(xn.x, xn.y);
    __nv_bfloat162 p1 = __floats2bfloat162_rn(xn.z, xn.w);
    uint2 pk;
    pk.x = *(uint32_t*)&p0;
    pk.y = *(uint32_t*)&p1;
    ((uint2*)(g_xnb + (size_t)row * D_MODEL))[t] = pk;

    float acc[NSTATE];
    #pragma unroll
    for (int nn = 0; nn < NSTATE; nn++) {
        const float4 wv = ((const float4*)(g_Wsum + nn * D_MODEL))[t];
        float a = xn.x * wv.x;
        a = fmaf(xn.y, wv.y, a);
        a = fmaf(xn.z, wv.z, a);
        a = fmaf(xn.w, wv.w, a);
        #pragma unroll
        for (int o = 16; o > 0; o >>= 1) a += __shfl_xor_sync(0xffffffffu, a, o);
        acc[nn] = a;
    }
    __shared__ float us[8][NSTATE];
    if (lid == 0) {
        #pragma unroll
        for (int nn = 0; nn < NSTATE; nn++) us[wid][nn] = acc[nn];
    }
    __syncthreads();
    if (t < NSTATE) {
        float ua = g_bsum[t];
        #pragma unroll
        for (int w = 0; w < 8; w++) ua += us[w][t];
        g_u[(size_t)row * NSTATE + t] = ua;
    }
}

// ---------------- K2: sequential scan h_t = tanh(A h_{t-1} + u_t) ----------------
__global__ __launch_bounds__(32) void k2_scan(const float* __restrict__ A) {
    const int lane = threadIdx.x;
    const int n = lane & 15;
    const int b = blockIdx.x * 2 + (lane >> 4);

    float Ar[16];
    #pragma unroll
    for (int j = 0; j < 16; j++) Ar[j] = A[n * 16 + j];

    const float* __restrict__ ub = g_u + (size_t)b * SEQ * NSTATE + n;
    float* __restrict__       Hb = g_H + (size_t)b * SEQ * NSTATE + n;

    float h = 0.f;
    float ur[8];
    #pragma unroll
    for (int k = 0; k < 8; k++) ur[k] = ub[k * NSTATE];

    #pragma unroll 1
    for (int t0 = 0; t0 < SEQ; t0 += 8) {
        #pragma unroll
        for (int k = 0; k < 8; k++) {
            float pre = ur[k];
            const int tn = t0 + 8 + k;
            if (tn < SEQ) ur[k] = ub[(size_t)tn * NSTATE];

            float a0 = 0.f, a1 = 0.f, a2 = 0.f, a3 = 0.f;
            #pragma unroll
            for (int j = 0; j < 4; j++) {
                a0 = fmaf(Ar[j +  0], __shfl_sync(0xffffffffu, h, j +  0, 16), a0);
                a1 = fmaf(Ar[j +  4], __shfl_sync(0xffffffffu, h, j +  4, 16), a1);
                a2 = fmaf(Ar[j +  8], __shfl_sync(0xffffffffu, h, j +  8, 16), a2);
                a3 = fmaf(Ar[j + 12], __shfl_sync(0xffffffffu, h, j + 12, 16), a3);
            }
            pre += (a0 + a1) + (a2 + a3);
            asm("tanh.approx.f32 %0, %1;" : "=f"(h) : "f"(pre));
            Hb[(size_t)(t0 + k) * NSTATE] = h;
        }
    }
}

// ---------------- K3: bf16 HMMA GEMM + fused (H@Wo^T+bo), gate, residual ----------------
// gate_pre = xn @ Wg^T ; y = sigmoid(gate_pre + bg) * (H@Wo^T + bo) + x
// CTA tile 128(M) x 128(N), K-chunk 64, 8 warps (2M x 4N), warp tile 64x32.
#define CHK      64
#define NCHK     (D_MODEL / CHK)        // 16
#define TILE_B   16384                  // 128 rows x 128 bytes
#define SMEM_TOT 65536

__device__ __forceinline__ void ldsm_x4(uint32_t* r, uint32_t addr) {
    asm volatile("ldmatrix.sync.aligned.m8n8.x4.shared.b16 {%0,%1,%2,%3}, [%4];"
                 : "=r"(r[0]), "=r"(r[1]), "=r"(r[2]), "=r"(r[3]) : "r"(addr));
}
__device__ __forceinline__ void mma16816(float* d, const uint32_t* a, const uint32_t* b) {
    asm volatile("mma.sync.aligned.m16n8k16.row.col.f32.bf16.bf16.f32 "
                 "{%0,%1,%2,%3}, {%4,%5,%6,%7}, {%8,%9}, {%0,%1,%2,%3};"
                 : "+f"(d[0]), "+f"(d[1]), "+f"(d[2]), "+f"(d[3])
                 : "r"(a[0]), "r"(a[1]), "r"(a[2]), "r"(a[3]), "r"(b[0]), "r"(b[1]));
}

__global__ __launch_bounds__(256, 2) void k3_gemm(const float* __restrict__ bg,
                                                  const float* __restrict__ bo,
                                                  const float* __restrict__ Wo,
                                                  const float* __restrict__ x,
                                                  float* __restrict__ out) {
    extern __shared__ char smem[];
    const uint32_t sbase = smem_u32(smem);

    const int tid  = threadIdx.x;
    const int wid  = tid >> 5;
    const int lane = tid & 31;
    const int wm   = wid >> 2;          // 0..1
    const int wn   = wid & 3;           // 0..3
    const int n0   = blockIdx.x * 128;
    const int m0   = blockIdx.y * 128;

    const __nv_bfloat16* Ag = g_xnb + (size_t)m0 * D_MODEL;
    const __nv_bfloat16* Bg = g_Wgb + (size_t)n0 * D_MODEL;

    // gmem staging: this thread's 4 chunks per matrix
    int ldRow[4], ldOff[4];
    #pragma unroll
    for (int i = 0; i < 4; i++) {
        const int u = tid + i * 256;
        const int row = u >> 3, c16 = u & 7;
        ldRow[i] = row;
        ldOff[i] = row * 128 + ((c16 ^ (row & 7)) << 4);
    }
    const int ldCol0[4] = { ((tid >> 0) & 7) * 8, (((tid + 256) & 2047) & 7) * 8,
                            (((tid + 512) & 2047) & 7) * 8, (((tid + 768) & 2047) & 7) * 8 };

    float acc[64];
    #pragma unroll
    for (int i = 0; i < 64; i++) acc[i] = 0.f;

    // ldmatrix lane addressing (offsets within a tile buffer)
    int aRowOff[4], aXor[4];
    #pragma unroll
    for (int tm = 0; tm < 4; tm++) {
        const int r = wm * 64 + tm * 16 + (lane & 15);
        aRowOff[tm] = r * 128;
        aXor[tm]    = r & 7;
    }
    const int aHi = lane >> 4;          // 0/1
    int bRowOff[2], bXor[2];
    #pragma unroll
    for (int tp = 0; tp < 2; tp++) {
        const int r = wn * 32 + tp * 16 + (lane & 7) + ((lane >> 4) << 3);
        bRowOff[tp] = r * 128;
        bXor[tp]    = r & 7;
    }
    const int bHi = (lane >> 3) & 1;    // 0/1

    // prologue: chunk 0 -> buffer 0
    {
        #pragma unroll
        for (int i = 0; i < 4; i++) {
            const uint4 va = *(const uint4*)(Ag + (size_t)ldRow[i] * D_MODEL + ldCol0[i]);
            const uint4 vb = *(const uint4*)(Bg + (size_t)ldRow[i] * D_MODEL + ldCol0[i]);
            *(uint4*)(smem + ldOff[i]) = va;
            *(uint4*)(smem + 32768 + ldOff[i]) = vb;
        }
    }
    __syncthreads();

    #pragma unroll 1
    for (int c = 0; c < NCHK; c++) {
        const int buf = c & 1;
        uint4 pa[4], pb[4];
        if (c + 1 < NCHK) {
            const int cc = (c + 1) * CHK;
            #pragma unroll
            for (int i = 0; i < 4; i++) {
                pa[i] = *(const uint4*)(Ag + (size_t)ldRow[i] * D_MODEL + cc + ldCol0[i]);
                pb[i] = *(const uint4*)(Bg + (size_t)ldRow[i] * D_MODEL + cc + ldCol0[i]);
            }
        }
        const uint32_t abase = sbase + buf * TILE_B;
        const uint32_t bbase = sbase + 32768 + buf * TILE_B;
        #pragma unroll
        for (int s = 0; s < 4; s++) {
            uint32_t ra[4][4], rb[2][4];
            #pragma unroll
            for (int tm = 0; tm < 4; tm++)
                ldsm_x4(ra[tm], abase + aRowOff[tm] + ((((s << 1) + aHi) ^ aXor[tm]) << 4));
            #pragma unroll
            for (int tp = 0; tp < 2; tp++)
                ldsm_x4(rb[tp], bbase + bRowOff[tp] + ((((s << 1) + bHi) ^ bXor[tp]) << 4));
            #pragma unroll
            for (int tm = 0; tm < 4; tm++)
                #pragma unroll
                for (int tn = 0; tn < 4; tn++)
                    mma16816(&acc[(tm * 4 + tn) * 4], ra[tm], &rb[tn >> 1][(tn & 1) * 2]);
        }
        if (c + 1 < NCHK) {
            const int ob = (buf ^ 1);
            #pragma unroll
            for (int i = 0; i < 4; i++) {
                *(uint4*)(smem + ob * TILE_B + ldOff[i]) = pa[i];
                *(uint4*)(smem + 32768 + ob * TILE_B + ldOff[i]) = pb[i];
            }
        }
        __syncthreads();
    }

    // ---- epilogue: overlay smem with H/Wo tiles ----
    float* hsf  = (float*)smem;                  // [128][20]
    float* wosf = (float*)(smem + 10240);        // [128][20]
    float* bos  = (float*)(smem + 20480);        // [128]
    float* bgs  = (float*)(smem + 21504);        // [128]

    #pragma unroll
    for (int i = 0; i < 2; i++) {
        const int idx = tid + i * 256;           // 0..511
        const int row = idx >> 2, k4 = idx & 3;
        const float4 hv = *(const float4*)(g_H + (size_t)(m0 + row) * NSTATE + k4 * 4);
        const float4 wv = *(const float4*)(Wo  + (size_t)(n0 + row) * NSTATE + k4 * 4);
        *(float4*)(hsf  + row * 20 + k4 * 4) = hv;
        *(float4*)(wosf + row * 20 + k4 * 4) = wv;
    }
    if (tid < 128) { bos[tid] = bo[n0 + tid]; bgs[tid] = bg[n0 + tid]; }
    __syncthreads();

    const int lr = lane >> 2;
    const int lc = (lane & 3) * 2;
    #pragma unroll
    for (int tm = 0; tm < 4; tm++) {
        #pragma unroll
        for (int half = 0; half < 2; half++) {
            const int m = wm * 64 + tm * 16 + half * 8 + lr;
            const float4 h0 = *(const float4*)(hsf + m * 20 + 0);
            const float4 h1 = *(const float4*)(hsf + m * 20 + 4);
            const float4 h2 = *(const float4*)(hsf + m * 20 + 8);
            const float4 h3 = *(const float4*)(hsf + m * 20 + 12);
            const float* xrow = x   + (size_t)(m0 + m) * D_MODEL + n0;
            float*       orow = out + (size_t)(m0 + m) * D_MODEL + n0;
            #pragma unroll
            for (int tn = 0; tn < 4; tn++) {
                const int n  = wn * 32 + tn * 8 + lc;
                const int ai = (tm * 4 + tn) * 4 + half * 2;
                float ov[2];
                #pragma unroll
                for (int cpair = 0; cpair < 2; cpair++) {
                    const float* w = wosf + (n + cpair) * 20;
                    const float4 w0 = *(const float4*)(w + 0);
                    const float4 w1 = *(const float4*)(w + 4);
                    const float4 w2 = *(const float4*)(w + 8);
                    const float4 w3 = *(const float4*)(w + 12);
                    float d = bos[n + cpair];
                    d = fmaf(h0.x, w0.x, d); d = fmaf(h0.y, w0.y, d);
                    d = fmaf(h0.z, w0.z, d); d = fmaf(h0.w, w0.w, d);
                    d = fmaf(h1.x, w1.x, d); d = fmaf(h1.y, w1.y, d);
                    d = fmaf(h1.z, w1.z, d); d = fmaf(h1.w, w1.w, d);
                    d = fmaf(h2.x, w2.x, d); d = fmaf(h2.y, w2.y, d);
                    d = fmaf(h2.z, w2.z, d); d = fmaf(h2.w, w2.w, d);
                    d = fmaf(h3.x, w3.x, d); d = fmaf(h3.y, w3.y, d);
                    d = fmaf(h3.z, w3.z, d); d = fmaf(h3.w, w3.w, d);
                    ov[cpair] = d;
                }
                const float2 xv = *(const float2*)(xrow + n);
                const float p0 = acc[ai + 0] + bgs[n + 0];
                const float p1 = acc[ai + 1] + bgs[n + 1];
                const float g0 = 1.f / (1.f + __expf(-p0));
                const float g1 = 1.f / (1.f + __expf(-p1));
                float2 y;
                y.x = fmaf(ov[0], g0, xv.x);
                y.y = fmaf(ov[1], g1, xv.y);
                *(float2*)(orow + n) = y;
            }
        }
    }
}

// ---------------- launch ----------------
extern "C" void kernel_launch(void* const* d_in, const int* in_sizes, int n_in,
                              void* d_out, int out_size) {
    const float* x    = (const float*)d_in[0];
    const float* Ws   = (const float*)d_in[1];
    const float* bs   = (const float*)d_in[2];
    const float* Wi   = (const float*)d_in[3];
    const float* bi   = (const float*)d_in[4];
    const float* Wo   = (const float*)d_in[5];
    const float* bo   = (const float*)d_in[6];
    const float* Wg   = (const float*)d_in[7];
    const float* bg   = (const float*)d_in[8];
    const float* ln_w = (const float*)d_in[9];
    const float* ln_b = (const float*)d_in[10];
    const float* A    = (const float*)d_in[11];
    float* out = (float*)d_out;

    cudaFuncSetAttribute(k3_gemm, cudaFuncAttributeMaxDynamicSharedMemorySize, SMEM_TOT);

    k0_prep<<<4096, 256>>>(Ws, Wi, bs, bi, Wg);
    k1_ln_u<<<ROWS, 256>>>(x, ln_w, ln_b);
    k2_scan<<<4, 32>>>(A);
    k3_gemm<<<dim3(D_MODEL / 128, ROWS / 128), 256, SMEM_TOT>>>(bg, bo, Wo, x, out);
}